// round 2
// baseline (speedup 1.0000x reference)
#include <cuda_runtime.h>
#include <math.h>

// Problem constants
#define Bn 2
#define Nn 1024
#define Dn 1024
#define Hn 16
#define HDn 64
#define BHn 32
#define NBn 16   // number of 64-row blocks along sequence

// ---------------- device scratch (module-static, no runtime allocs) ----------------
__device__ float g_qf[Bn*Nn*Dn];
__device__ float g_kf[Bn*Nn*Dn];
__device__ float g_vf[Bn*Nn*Dn];
__device__ float g_wf[Bn*Nn*Dn];
__device__ float g_w1[Bn*Nn*HDn];
__device__ float g_bb[Bn*Nn*Hn];
__device__ float g_ff[Bn*Nn*Hn];

__device__ float g_q[BHn*Nn*HDn];   // [bh][n][hd]
__device__ float g_k[BHn*Nn*HDn];
__device__ float g_v[BHn*Nn*HDn];
__device__ float g_w[BHn*Nn*HDn];
__device__ float g_beta[BHn*Nn];
__device__ float g_lf[BHn*Nn];
__device__ float g_Fc[BHn*Nn];
__device__ float g_Tinv[BHn*NBn*64*64];        // (I+L_ii)^-1, full 64x64 with zeros
__device__ float g_LG[(size_t)BHn*Nn*Nn];      // L blocks during solve; dense G afterwards
__device__ float g_C[(size_t)BHn*Nn*Nn];       // UT-transform solution
__device__ float g_S[(size_t)BHn*Nn*Nn];       // logits -> P in place
__device__ float g_o[Bn*Nn*Dn];                // attention output before Wo

// ---------------- 64x64 tile helpers (256 threads/block) ----------------

// Load a 64x64 fp32 tile (row stride 'stride' floats) into padded smem.
__device__ __forceinline__ void load_tile(float (*sm)[65], const float* __restrict__ g, int stride) {
    int t = threadIdx.x;
    int r = t >> 2;              // 0..63
    int c0 = (t & 3) << 4;       // 0,16,32,48
    const float* gp = g + (size_t)r * stride + c0;
#pragma unroll
    for (int q = 0; q < 4; q++) {
        float4 v = *(const float4*)(gp + q * 4);
        sm[r][c0 + 4*q + 0] = v.x;
        sm[r][c0 + 4*q + 1] = v.y;
        sm[r][c0 + 4*q + 2] = v.z;
        sm[r][c0 + 4*q + 3] = v.w;
    }
}

// acc[i][j] += sum_k A[row][k]*B[k][col]   (NN)
template<int SGN>
__device__ __forceinline__ void mma_nn(float acc[4][4], const float (*Am)[65], const float (*Bm)[65]) {
    int ty = ((threadIdx.x >> 4) << 2);
    int tx = ((threadIdx.x & 15) << 2);
#pragma unroll 8
    for (int kk = 0; kk < 64; kk++) {
        float a[4], b[4];
#pragma unroll
        for (int i = 0; i < 4; i++) a[i] = Am[ty + i][kk];
#pragma unroll
        for (int j = 0; j < 4; j++) b[j] = Bm[kk][tx + j];
#pragma unroll
        for (int i = 0; i < 4; i++)
#pragma unroll
            for (int j = 0; j < 4; j++) {
                if (SGN > 0) acc[i][j] += a[i] * b[j];
                else         acc[i][j] -= a[i] * b[j];
            }
    }
}

// acc[i][j] += sum_k A[row][k]*B[col][k]   (NT: dot of rows)
__device__ __forceinline__ void mma_nt(float acc[4][4], const float (*Am)[65], const float (*Bm)[65]) {
    int ty = ((threadIdx.x >> 4) << 2);
    int tx = ((threadIdx.x & 15) << 2);
#pragma unroll 8
    for (int kk = 0; kk < 64; kk++) {
        float a[4], b[4];
#pragma unroll
        for (int i = 0; i < 4; i++) a[i] = Am[ty + i][kk];
#pragma unroll
        for (int j = 0; j < 4; j++) b[j] = Bm[tx + j][kk];
#pragma unroll
        for (int i = 0; i < 4; i++)
#pragma unroll
            for (int j = 0; j < 4; j++)
                acc[i][j] += a[i] * b[j];
    }
}

// ---------------- generic tiled GEMM: C[MxN] = A[MxK] @ B[KxN] (row-major) ----------------
// 64x64 tile per block, K-step 16, 256 threads, 4x4 microtile. M%64==0, K%16==0. N guarded.
__global__ void gemm_kernel(const float* __restrict__ A, const float* __restrict__ Bm,
                            float* __restrict__ C, int M, int Ncols, int K) {
    __shared__ float As[16][65];
    __shared__ float Bs[16][65];
    int m0 = blockIdx.y * 64, n0 = blockIdx.x * 64;
    int tid = threadIdx.x;
    int ty = (tid >> 4) << 2, tx = (tid & 15) << 2;
    int lrA = tid >> 2, lcA = (tid & 3) << 2;
    int krB = tid >> 4, ncB = (tid & 15) << 2;
    float acc[4][4] = {};
    for (int k0 = 0; k0 < K; k0 += 16) {
        float4 va = *(const float4*)(A + (size_t)(m0 + lrA) * K + k0 + lcA);
        As[lcA + 0][lrA] = va.x;
        As[lcA + 1][lrA] = va.y;
        As[lcA + 2][lrA] = va.z;
        As[lcA + 3][lrA] = va.w;
#pragma unroll
        for (int q = 0; q < 4; q++) {
            int col = n0 + ncB + q;
            Bs[krB][ncB + q] = (col < Ncols) ? Bm[(size_t)(k0 + krB) * Ncols + col] : 0.f;
        }
        __syncthreads();
#pragma unroll
        for (int kk = 0; kk < 16; kk++) {
            float a[4], b[4];
#pragma unroll
            for (int i = 0; i < 4; i++) a[i] = As[kk][ty + i];
#pragma unroll
            for (int j = 0; j < 4; j++) b[j] = Bs[kk][tx + j];
#pragma unroll
            for (int i = 0; i < 4; i++)
#pragma unroll
                for (int j = 0; j < 4; j++)
                    acc[i][j] += a[i] * b[j];
        }
        __syncthreads();
    }
#pragma unroll
    for (int i = 0; i < 4; i++)
#pragma unroll
        for (int j = 0; j < 4; j++) {
            int col = n0 + tx + j;
            if (col < Ncols) C[(size_t)(m0 + ty + i) * Ncols + col] = acc[i][j];
        }
}

// ---------------- reorg: head layout, w-normalize, beta, log-sigmoid gate ----------------
__global__ void reorg_kernel(const float* __restrict__ delta) {
    int bn = blockIdx.x;            // 0..2047
    int b = bn >> 10, n = bn & 1023;
    int tid = threadIdx.x;
    __shared__ float wrow[Dn];
    __shared__ float rn[Hn];
    for (int e = tid; e < Dn; e += 256) {
        int h = e >> 6, c = e & 63;
        int src = bn * Dn + e;
        int dst = ((b * Hn + h) * Nn + n) * HDn + c;
        g_q[dst] = g_qf[src];
        g_k[dst] = g_kf[src];
        g_v[dst] = g_vf[src];
        wrow[e] = g_wf[src];
    }
    __syncthreads();
    if (tid < Hn) {
        float s = 1e-6f;
        for (int c = 0; c < HDn; c++) { float w = wrow[tid * HDn + c]; s += w * w; }
        rn[tid] = rsqrtf(s);
        float bbv = g_bb[bn * Hn + tid];
        g_beta[(b * Hn + tid) * Nn + n] = 2.f / (1.f + expf(-bbv));
        float z = g_ff[bn * Hn + tid] + delta[tid];
        g_lf[(b * Hn + tid) * Nn + n] = fminf(z, 0.f) - log1pf(expf(-fabsf(z)));
    }
    __syncthreads();
    for (int e = tid; e < Dn; e += 256) {
        int h = e >> 6, c = e & 63;
        g_w[((b * Hn + h) * Nn + n) * HDn + c] = wrow[e] * rn[h];
    }
}

// ---------------- cumulative sum of log gates per (b,h) ----------------
__global__ void cumsum_kernel() {
    int bh = blockIdx.x, tid = threadIdx.x;
    __shared__ float part[256];
    const float* lf = g_lf + bh * Nn;
    float v0 = lf[tid * 4 + 0];
    float v1 = lf[tid * 4 + 1];
    float v2 = lf[tid * 4 + 2];
    float v3 = lf[tid * 4 + 3];
    v1 += v0; v2 += v1; v3 += v2;
    part[tid] = v3;
    __syncthreads();
    if (tid == 0) {
        float run = 0.f;
        for (int t = 0; t < 256; t++) { float tmp = part[t]; part[t] = run; run += tmp; }
    }
    __syncthreads();
    float off = part[tid];
    g_Fc[bh * Nn + tid * 4 + 0] = off + v0;
    g_Fc[bh * Nn + tid * 4 + 1] = off + v1;
    g_Fc[bh * Nn + tid * 4 + 2] = off + v2;
    g_Fc[bh * Nn + tid * 4 + 3] = off + v3;
}

// ---------------- L blocks: L[i][r] = (w_i @ w_r^T) * beta_r  (r < i only) ----------------
__global__ void l_kernel() {
    int bx = blockIdx.x;
    int i = bx >> 4, r = bx & 15;
    if (r >= i) return;
    int bh = blockIdx.y;
    __shared__ float smA[64][65], smB[64][65];
    load_tile(smA, g_w + ((size_t)bh * Nn + i * 64) * HDn, HDn);
    load_tile(smB, g_w + ((size_t)bh * Nn + r * 64) * HDn, HDn);
    __syncthreads();
    float acc[4][4] = {};
    mma_nt(acc, smA, smB);
    int ty = ((threadIdx.x >> 4) << 2), tx = ((threadIdx.x & 15) << 2);
    float* out = g_LG + (((size_t)bh * NBn + i) * NBn + r) * 4096;
#pragma unroll
    for (int a = 0; a < 4; a++)
#pragma unroll
        for (int b2 = 0; b2 < 4; b2++) {
            int ro = ty + a, co = tx + b2;
            out[ro * 64 + co] = acc[a][b2] * g_beta[bh * Nn + r * 64 + co];
        }
}

// ---------------- Tinv: (I + L_ii)^-1 per diagonal block ----------------
__global__ void tinv_kernel() {
    int i = blockIdx.x, bh = blockIdx.y, tid = threadIdx.x;
    __shared__ float smW[64][65];
    __shared__ float smA[64][65];
    float (*X)[65] = smW;   // reuse smW storage for the solve
    load_tile(smW, g_w + ((size_t)bh * Nn + i * 64) * HDn, HDn);
    __syncthreads();
    float acc[4][4] = {};
    mma_nt(acc, smW, smW);
    int ty = ((tid >> 4) << 2), tx = ((tid & 15) << 2);
#pragma unroll
    for (int a = 0; a < 4; a++)
#pragma unroll
        for (int b2 = 0; b2 < 4; b2++) {
            int s = ty + a, r = tx + b2;
            smA[s][r] = (r < s) ? acc[a][b2] * g_beta[bh * Nn + i * 64 + r] : 0.f;
        }
    __syncthreads();   // smA ready; smW free to be overwritten as X
    if (tid < 64) {
        int c = tid;
        X[c][c] = 1.f;
        for (int rr = c + 1; rr < 64; rr++) {
            float s = 0.f;
            for (int m = c; m < rr; m++) s += smA[rr][m] * X[m][c];
            X[rr][c] = -s;
        }
    }
    __syncthreads();
    float* out = g_Tinv + ((size_t)bh * NBn + i) * 4096;
    for (int e = tid; e < 4096; e += 256) {
        int rr = e >> 6, cc = e & 63;
        out[e] = (rr > cc) ? X[rr][cc] : (rr == cc ? 1.f : 0.f);
    }
}

// ---------------- solve step (block row i): C_ij = Tinv_i (M_ij - sum_r L_ir C_rj) ----------------
__global__ void solve_kernel(int i) {
    int j = blockIdx.x;      // 0..i
    int bh = blockIdx.y;
    int tid = threadIdx.x;
    int ty = ((tid >> 4) << 2), tx = ((tid & 15) << 2);
    __shared__ float smA[64][65], smB[64][65];
    float acc[4][4] = {};
    // M_ij = w_i @ k_j^T (strict tril when i==j)
    load_tile(smA, g_w + ((size_t)bh * Nn + i * 64) * HDn, HDn);
    load_tile(smB, g_k + ((size_t)bh * Nn + j * 64) * HDn, HDn);
    __syncthreads();
    mma_nt(acc, smA, smB);
    if (i == j) {
#pragma unroll
        for (int a = 0; a < 4; a++)
#pragma unroll
            for (int b2 = 0; b2 < 4; b2++)
                if ((ty + a) <= (tx + b2)) acc[a][b2] = 0.f;
    }
    for (int r = j; r < i; r++) {
        __syncthreads();
        load_tile(smA, g_LG + (((size_t)bh * NBn + i) * NBn + r) * 4096, 64);
        load_tile(smB, g_C + ((size_t)bh * Nn + r * 64) * Nn + j * 64, Nn);
        __syncthreads();
        mma_nn<-1>(acc, smA, smB);
    }
    __syncthreads();
    // R -> smB, Tinv -> smA, C_ij = Tinv @ R
#pragma unroll
    for (int a = 0; a < 4; a++)
#pragma unroll
        for (int b2 = 0; b2 < 4; b2++)
            smB[ty + a][tx + b2] = acc[a][b2];
    load_tile(smA, g_Tinv + ((size_t)bh * NBn + i) * 4096, 64);
    __syncthreads();
    float acc2[4][4] = {};
    mma_nn<1>(acc2, smA, smB);
    float* out = g_C + ((size_t)bh * Nn + i * 64) * Nn + j * 64;
#pragma unroll
    for (int a = 0; a < 4; a++)
#pragma unroll
        for (int b2 = 0; b2 < 4; b2++)
            out[(ty + a) * Nn + tx + b2] = acc2[a][b2];
}

// ---------------- G = tril(q w^T) * beta_s  (dense into g_LG, reusing L's storage) ----------------
__global__ void g_kernel() {
    int bx = blockIdx.x;
    int ti = bx >> 4, tj = bx & 15;
    if (tj > ti) return;
    int bh = blockIdx.y;
    __shared__ float smA[64][65], smB[64][65];
    load_tile(smA, g_q + ((size_t)bh * Nn + ti * 64) * HDn, HDn);
    load_tile(smB, g_w + ((size_t)bh * Nn + tj * 64) * HDn, HDn);
    __syncthreads();
    float acc[4][4] = {};
    mma_nt(acc, smA, smB);
    int ty = ((threadIdx.x >> 4) << 2), tx = ((threadIdx.x & 15) << 2);
    float* out = g_LG + (size_t)bh * Nn * Nn + (size_t)(ti * 64) * Nn + tj * 64;
#pragma unroll
    for (int a = 0; a < 4; a++)
#pragma unroll
        for (int b2 = 0; b2 < 4; b2++) {
            int ro = ty + a, co = tx + b2;
            float val = acc[a][b2] * g_beta[bh * Nn + tj * 64 + co];
            if (ti == tj && co > ro) val = 0.f;
            out[ro * Nn + co] = val;
        }
}

// ---------------- logits: S = (qk^T - G C)*scale + Fc_t - Fc_j ----------------
__global__ void s_kernel() {
    int bx = blockIdx.x;
    int ti = bx >> 4, tj = bx & 15;
    if (tj > ti) return;
    int bh = blockIdx.y;
    __shared__ float smA[64][65], smB[64][65];
    load_tile(smA, g_q + ((size_t)bh * Nn + ti * 64) * HDn, HDn);
    load_tile(smB, g_k + ((size_t)bh * Nn + tj * 64) * HDn, HDn);
    __syncthreads();
    float acc[4][4] = {};
    mma_nt(acc, smA, smB);
    for (int sb = tj; sb <= ti; sb++) {
        __syncthreads();
        load_tile(smA, g_LG + (size_t)bh * Nn * Nn + (size_t)(ti * 64) * Nn + sb * 64, Nn);
        load_tile(smB, g_C + (size_t)bh * Nn * Nn + (size_t)(sb * 64) * Nn + tj * 64, Nn);
        __syncthreads();
        mma_nn<-1>(acc, smA, smB);
    }
    int ty = ((threadIdx.x >> 4) << 2), tx = ((threadIdx.x & 15) << 2);
#pragma unroll
    for (int a = 0; a < 4; a++)
#pragma unroll
        for (int b2 = 0; b2 < 4; b2++) {
            int t = ti * 64 + ty + a;
            int jg = tj * 64 + tx + b2;
            float val = acc[a][b2] * 0.125f + g_Fc[bh * Nn + t] - g_Fc[bh * Nn + jg];
            if (ti == tj && jg > t) val = -1e30f;
            g_S[(size_t)bh * Nn * Nn + (size_t)t * Nn + jg] = val;
        }
}

// ---------------- row softmax (in place on g_S, rows rounded up to tile boundary) ----------------
__global__ void softmax_kernel() {
    int t = blockIdx.x, bh = blockIdx.y, tid = threadIdx.x;
    float* row = g_S + (size_t)bh * Nn * Nn + (size_t)t * Nn;
    int Lr = ((t >> 6) + 1) << 6;
    __shared__ float red[4];
    float m = -3.4e38f;
    for (int idx = tid; idx < Lr; idx += 128) m = fmaxf(m, row[idx]);
#pragma unroll
    for (int o = 16; o; o >>= 1) m = fmaxf(m, __shfl_xor_sync(0xffffffffu, m, o));
    if ((tid & 31) == 0) red[tid >> 5] = m;
    __syncthreads();
    m = fmaxf(fmaxf(red[0], red[1]), fmaxf(red[2], red[3]));
    __syncthreads();
    float s = 0.f;
    for (int idx = tid; idx < Lr; idx += 128) {
        float e = expf(row[idx] - m);
        row[idx] = e;
        s += e;
    }
#pragma unroll
    for (int o = 16; o; o >>= 1) s += __shfl_xor_sync(0xffffffffu, s, o);
    if ((tid & 31) == 0) red[tid >> 5] = s;
    __syncthreads();
    s = red[0] + red[1] + red[2] + red[3];
    float inv = 1.f / s;
    for (int idx = tid; idx < Lr; idx += 128) row[idx] *= inv;
}

// ---------------- o = P @ v  (into (b,n,d) layout) ----------------
__global__ void pv_kernel() {
    int ti = blockIdx.x, bh = blockIdx.y;
    __shared__ float smA[64][65], smB[64][65];
    float acc[4][4] = {};
    for (int jb = 0; jb <= ti; jb++) {
        __syncthreads();
        load_tile(smA, g_S + (size_t)bh * Nn * Nn + (size_t)(ti * 64) * Nn + jb * 64, Nn);
        load_tile(smB, g_v + ((size_t)bh * Nn + jb * 64) * HDn, HDn);
        __syncthreads();
        mma_nn<1>(acc, smA, smB);
    }
    int b = bh >> 4, h = bh & 15;
    int ty = ((threadIdx.x >> 4) << 2), tx = ((threadIdx.x & 15) << 2);
#pragma unroll
    for (int a = 0; a < 4; a++)
#pragma unroll
        for (int b2 = 0; b2 < 4; b2++)
            g_o[(size_t)(b * Nn + ti * 64 + ty + a) * Dn + h * 64 + tx + b2] = acc[a][b2];
}

// ---------------- launch ----------------
extern "C" void kernel_launch(void* const* d_in, const int* in_sizes, int n_in,
                              void* d_out, int out_size) {
    const float* x   = (const float*)d_in[0];
    const float* Wq  = (const float*)d_in[1];
    const float* Wk  = (const float*)d_in[2];
    const float* Wv  = (const float*)d_in[3];
    const float* Wo  = (const float*)d_in[4];
    const float* Ww1 = (const float*)d_in[5];
    const float* Ww2 = (const float*)d_in[6];
    const float* Wb  = (const float*)d_in[7];
    const float* Wf  = (const float*)d_in[8];
    const float* dl  = (const float*)d_in[9];
    float* out = (float*)d_out;

    // Resolve scratch symbol addresses once per process.
    static float *qf, *kf, *vf, *wf, *w1, *bb, *ff, *o_;
    static bool init = false;
    if (!init) {
        void* p;
        cudaGetSymbolAddress(&p, g_qf); qf = (float*)p;
        cudaGetSymbolAddress(&p, g_kf); kf = (float*)p;
        cudaGetSymbolAddress(&p, g_vf); vf = (float*)p;
        cudaGetSymbolAddress(&p, g_wf); wf = (float*)p;
        cudaGetSymbolAddress(&p, g_w1); w1 = (float*)p;
        cudaGetSymbolAddress(&p, g_bb); bb = (float*)p;
        cudaGetSymbolAddress(&p, g_ff); ff = (float*)p;
        cudaGetSymbolAddress(&p, g_o);  o_ = (float*)p;
        init = true;
    }

    dim3 thr(256);
    const int M = Bn * Nn;  // 2048

    // projections
    gemm_kernel<<<dim3(16, 32), thr>>>(x,  Wq,  qf, M, 1024, 1024);
    gemm_kernel<<<dim3(16, 32), thr>>>(x,  Wk,  kf, M, 1024, 1024);
    gemm_kernel<<<dim3(16, 32), thr>>>(x,  Wv,  vf, M, 1024, 1024);
    gemm_kernel<<<dim3(1,  32), thr>>>(x,  Ww1, w1, M, 64,   1024);
    gemm_kernel<<<dim3(16, 32), thr>>>(w1, Ww2, wf, M, 1024, 64);
    gemm_kernel<<<dim3(1,  32), thr>>>(x,  Wb,  bb, M, 16, 1024);
    gemm_kernel<<<dim3(1,  32), thr>>>(x,  Wf,  ff, M, 16, 1024);

    reorg_kernel<<<2048, thr>>>(dl);
    cumsum_kernel<<<32, thr>>>();

    // L blocks + diagonal inverses
    l_kernel<<<dim3(256, 32), thr>>>();
    tinv_kernel<<<dim3(16, 32), thr>>>();

    // blocked forward substitution: 16 dependent steps
    for (int i = 0; i < NBn; i++)
        solve_kernel<<<dim3(i + 1, 32), thr>>>(i);

    // G (reuses L storage), logits, softmax, P@V
    g_kernel<<<dim3(256, 32), thr>>>();
    s_kernel<<<dim3(256, 32), thr>>>();
    softmax_kernel<<<dim3(1024, 32), dim3(128)>>>();
    pv_kernel<<<dim3(16, 32), thr>>>();

    // final projection straight into d_out
    gemm_kernel<<<dim3(16, 32), thr>>>(o_, Wo, out, M, 1024, 1024);
}